// round 14
// baseline (speedup 1.0000x reference)
#include <cuda_runtime.h>

#define B_ 16
#define T_ 2048
#define D_ 512
#define V_ 4096

// Scratch (static device globals — no allocation allowed in kernel_launch)
__device__ float g_p[B_ * T_];         // prob of argmax token per frame
__device__ int   g_pred[B_ * T_];      // argmax token per frame
__device__ int4  g_segmeta[B_ * T_];   // per (b,row): {start, len, bits(inv), 0}; len=0 => zero row
__device__ int   g_newlen[B_];         // per b: number of segments

// ---------------------------------------------------------------------------
// Kernel 1: per frame (B*T rows), argmax over V=4096 and p = 1/sum(exp(x-max))
// One block (256 thr) per row; max via FMNMX tree; index via exact equality.
// Measured at the sm_103a streaming ceiling (~6.59 TB/s, 83% DRAM).
// ---------------------------------------------------------------------------
__global__ __launch_bounds__(256) void argmax_p_kernel(const float* __restrict__ logits)
{
    const int r   = blockIdx.x;           // 0 .. B*T-1
    const int tid = threadIdx.x;
    const float4* row = reinterpret_cast<const float4*>(logits) + (size_t)r * (V_ / 4);

    // streaming loads (no reuse) — 4 LDG.128 in flight per thread
    const float4 v0 = __ldcs(&row[tid]);
    const float4 v1 = __ldcs(&row[tid + 256]);
    const float4 v2 = __ldcs(&row[tid + 512]);
    const float4 v3 = __ldcs(&row[tid + 768]);

    // thread-local max (pure FMNMX tree)
    const float m0 = fmaxf(fmaxf(v0.x, v0.y), fmaxf(v0.z, v0.w));
    const float m1 = fmaxf(fmaxf(v1.x, v1.y), fmaxf(v1.z, v1.w));
    const float m2 = fmaxf(fmaxf(v2.x, v2.y), fmaxf(v2.z, v2.w));
    const float m3 = fmaxf(fmaxf(v3.x, v3.y), fmaxf(v3.z, v3.w));
    float bv = fmaxf(fmaxf(m0, m1), fmaxf(m2, m3));

    const int lane = tid & 31, wid = tid >> 5;
#pragma unroll
    for (int o = 16; o; o >>= 1)
        bv = fmaxf(bv, __shfl_xor_sync(0xffffffffu, bv, o));

    __shared__ float s_w[8];
    __shared__ float s_m;
    if (lane == 0) s_w[wid] = bv;
    __syncthreads();
    if (tid < 8) {
        float x = s_w[tid];
#pragma unroll
        for (int o = 4; o; o >>= 1)
            x = fmaxf(x, __shfl_xor_sync(0xffu, x, o));
        if (tid == 0) s_m = x;
    }
    __syncthreads();

    const float m   = s_m;
    const float L2E = 1.4426950408889634f;
    const float mh  = m * L2E;

    float a0 = 0.f, a1 = 0.f, a2 = 0.f, a3 = 0.f;
    int   bi = 0x7fffffff;

#define ELEM(val, idx, acc)                                   \
    {                                                         \
        acc += exp2f(fmaf((val), L2E, -mh));                  \
        if ((val) == m) bi = min(bi, (idx));                  \
    }
    const int g0 = tid * 4, g1 = (tid + 256) * 4, g2 = (tid + 512) * 4, g3 = (tid + 768) * 4;
    ELEM(v0.x, g0 + 0, a0) ELEM(v0.y, g0 + 1, a1) ELEM(v0.z, g0 + 2, a2) ELEM(v0.w, g0 + 3, a3)
    ELEM(v1.x, g1 + 0, a0) ELEM(v1.y, g1 + 1, a1) ELEM(v1.z, g1 + 2, a2) ELEM(v1.w, g1 + 3, a3)
    ELEM(v2.x, g2 + 0, a0) ELEM(v2.y, g2 + 1, a1) ELEM(v2.z, g2 + 2, a2) ELEM(v2.w, g2 + 3, a3)
    ELEM(v3.x, g3 + 0, a0) ELEM(v3.y, g3 + 1, a1) ELEM(v3.z, g3 + 2, a2) ELEM(v3.w, g3 + 3, a3)
#undef ELEM

    float se = (a0 + a1) + (a2 + a3);
#pragma unroll
    for (int o = 16; o; o >>= 1) {
        se += __shfl_xor_sync(0xffffffffu, se, o);
        bi  = min(bi, __shfl_xor_sync(0xffffffffu, bi, o));
    }

    __shared__ float s_s[8];
    __shared__ int   s_i[8];
    if (lane == 0) { s_s[wid] = se; s_i[wid] = bi; }
    __syncthreads();
    if (tid < 8) {
        float S = s_s[tid];
        int   I = s_i[tid];
#pragma unroll
        for (int o = 4; o; o >>= 1) {
            S += __shfl_xor_sync(0xffu, S, o);
            I  = min(I, __shfl_xor_sync(0xffu, I, o));
        }
        if (tid == 0) {
            g_p[r]    = 1.0f / S;   // softmax prob at argmax == 1/sum(exp(x-max))
            g_pred[r] = I;
        }
    }
}

// ---------------------------------------------------------------------------
// Kernel 2: per batch row — segmentation; writes a DENSE metadata table
// (all T rows; sentinel len=0 past the last segment) so the gather kernel
// needs exactly one metadata load and zero branches.
// ---------------------------------------------------------------------------
__global__ __launch_bounds__(256) void seg_kernel(const int* __restrict__ lengths,
                                                  float* __restrict__ out_tail,
                                                  int write_tail)
{
    const int b   = blockIdx.x;
    const int tid = threadIdx.x;
    const int L   = lengths[b];
    const int* pred = g_pred + b * T_;
    const float* pp = g_p    + b * T_;

    __shared__ int   sh_start[T_];
    __shared__ float sh_segp[T_];
    __shared__ int   sh_last[256];
    __shared__ int   wtot[8];

    // vectorized pred load: 8 ints per thread
    const int4* pv = reinterpret_cast<const int4*>(pred + tid * 8);
    const int4  pa = pv[0];
    const int4  pb = pv[1];
    int pr[8] = {pa.x, pa.y, pa.z, pa.w, pb.x, pb.y, pb.z, pb.w};
    sh_last[tid] = pb.w;

    for (int i = tid; i < T_; i += 256) sh_segp[i] = 0.f;
    __syncthreads();

    const int t0 = tid * 8;
    int st[8], incl[8];
    int loc  = 0;
    int prev = (tid > 0) ? sh_last[tid - 1] : -1;
#pragma unroll
    for (int j = 0; j < 8; j++) {
        const int t = t0 + j;
        const int s = (t < L) && (t == 0 || pr[j] != prev);
        prev = pr[j];
        st[j] = s;
        loc  += s;
        incl[j] = loc;
    }

    // block-wide exclusive scan of per-thread start counts
    const int lane = tid & 31, wid = tid >> 5;
    int v = loc;
#pragma unroll
    for (int o = 1; o < 32; o <<= 1) {
        int n = __shfl_up_sync(0xffffffffu, v, o);
        if (lane >= o) v += n;
    }
    if (lane == 31) wtot[wid] = v;
    __syncthreads();
    if (tid < 8) {
        int w = wtot[tid];
#pragma unroll
        for (int o = 1; o < 8; o <<= 1) {
            int n = __shfl_up_sync(0xffu, w, o);
            if (tid >= o) w += n;
        }
        wtot[tid] = w;  // inclusive warp totals
    }
    __syncthreads();
    const int total = wtot[7];
    const int excl  = (wid ? wtot[wid - 1] : 0) + (v - loc);

    // vectorized p load
    const float4* pfv = reinterpret_cast<const float4*>(pp + tid * 8);
    const float4 f0 = pfv[0];
    const float4 f1 = pfv[1];
    const float pf[8] = {f0.x, f0.y, f0.z, f0.w, f1.x, f1.y, f1.z, f1.w};

    // per-frame segment id; record starts; accumulate seg_p
#pragma unroll
    for (int j = 0; j < 8; j++) {
        const int t = t0 + j;
        if (t < L) {
            const int sid = excl + incl[j] - 1;
            if (st[j]) sh_start[sid] = t;
            atomicAdd(&sh_segp[sid], pf[j]);
        }
    }
    __syncthreads();

    // dense metadata: valid segments get {start, len, inv}; rest get len=0
    for (int s = tid; s < T_; s += 256) {
        int4 mt;
        if (s < total) {
            const int start = sh_start[s];
            const int next  = (s + 1 < total) ? sh_start[s + 1] : L;
            mt = make_int4(start, next - start,
                           __float_as_int(1.0f / (sh_segp[s] + 1e-10f)), 0);
        } else {
            mt = make_int4(0, 0, 0, 0);
        }
        g_segmeta[b * T_ + s] = mt;
    }
    if (tid == 0) {
        g_newlen[b] = total;
        if (write_tail) out_tail[b] = (float)total;
    }
}

// ---------------------------------------------------------------------------
// Kernel 3: one WARP per output row (b, s); 8 rows per 256-thread block.
// Branch-free: len=0 rows fall through the loop and store zeros.
// Dependent chain: meta -> (p, hidden) -> store; p reads are L2-hot.
// ---------------------------------------------------------------------------
__global__ __launch_bounds__(256) void gather_kernel(const float* __restrict__ hidden,
                                                     float* __restrict__ out)
{
    const int warp = threadIdx.x >> 5;
    const int lane = threadIdx.x & 31;
    const int row  = blockIdx.x * 8 + warp;     // 0 .. B*T-1  (8 divides T)
    const int b    = row >> 11;                 // row / T_

    const int4  mt    = __ldg(&g_segmeta[row]);
    const int   start = mt.x;
    const int   len   = mt.y;
    const float inv   = __int_as_float(mt.z);

    const float4* hrow =
        reinterpret_cast<const float4*>(hidden) + ((size_t)(b * T_ + start)) * (D_ / 4);
    const float* pbase = g_p + b * T_ + start;

    float4 acc[4] = {make_float4(0.f, 0.f, 0.f, 0.f), make_float4(0.f, 0.f, 0.f, 0.f),
                     make_float4(0.f, 0.f, 0.f, 0.f), make_float4(0.f, 0.f, 0.f, 0.f)};
    for (int f = 0; f < len; ++f) {
        const float w = pbase[f] * inv;
#pragma unroll
        for (int k = 0; k < 4; k++) {
            const float4 h = __ldcs(&hrow[f * (D_ / 4) + lane + k * 32]);
            acc[k].x += w * h.x;
            acc[k].y += w * h.y;
            acc[k].z += w * h.z;
            acc[k].w += w * h.w;
        }
    }

    float4* orow = reinterpret_cast<float4*>(out) + (size_t)row * (D_ / 4);
#pragma unroll
    for (int k = 0; k < 4; k++) __stcs(&orow[lane + k * 32], acc[k]);
}

// ---------------------------------------------------------------------------
extern "C" void kernel_launch(void* const* d_in, const int* in_sizes, int n_in,
                              void* d_out, int out_size)
{
    const float* hidden  = (const float*)d_in[0];  // (B,T,D) f32
    const float* logits  = (const float*)d_in[1];  // (B,T,V) f32
    const int*   lengths = (const int*)d_in[2];    // (B,)   i32
    float* out = (float*)d_out;

    argmax_p_kernel<<<B_ * T_, 256>>>(logits);

    const int main_elems = B_ * T_ * D_;
    const int write_tail = (out_size >= main_elems + B_) ? 1 : 0;
    seg_kernel<<<B_, 256>>>(lengths, out + (size_t)main_elems, write_tail);

    gather_kernel<<<(B_ * T_) / 8, 256>>>(hidden, out);
}

// round 15
// speedup vs baseline: 1.0106x; 1.0106x over previous
#include <cuda_runtime.h>

#define B_ 16
#define T_ 2048
#define D_ 512
#define V_ 4096

// Scratch (static device globals — no allocation allowed in kernel_launch)
__device__ float g_p[B_ * T_];         // prob of argmax token per frame
__device__ int   g_pred[B_ * T_];      // argmax token per frame
__device__ int4  g_segmeta[B_ * T_];   // per (b,row): {start, len, bits(inv), 0}; len=0 => zero row
__device__ int   g_newlen[B_];         // per b: number of segments

// ---------------------------------------------------------------------------
// Kernel 1: per frame (B*T rows), argmax over V=4096 and p = 1/sum(exp(x-max))
// One block (256 thr) per row; max via FMNMX tree; index via exact equality.
// Measured at the sm_103a streaming ceiling (~6.55 TB/s, 82-83% DRAM).
// ---------------------------------------------------------------------------
__global__ __launch_bounds__(256) void argmax_p_kernel(const float* __restrict__ logits)
{
    const int r   = blockIdx.x;           // 0 .. B*T-1
    const int tid = threadIdx.x;
    const float4* row = reinterpret_cast<const float4*>(logits) + (size_t)r * (V_ / 4);

    // streaming loads (no reuse) — 4 LDG.128 in flight per thread
    const float4 v0 = __ldcs(&row[tid]);
    const float4 v1 = __ldcs(&row[tid + 256]);
    const float4 v2 = __ldcs(&row[tid + 512]);
    const float4 v3 = __ldcs(&row[tid + 768]);

    // thread-local max (pure FMNMX tree)
    const float m0 = fmaxf(fmaxf(v0.x, v0.y), fmaxf(v0.z, v0.w));
    const float m1 = fmaxf(fmaxf(v1.x, v1.y), fmaxf(v1.z, v1.w));
    const float m2 = fmaxf(fmaxf(v2.x, v2.y), fmaxf(v2.z, v2.w));
    const float m3 = fmaxf(fmaxf(v3.x, v3.y), fmaxf(v3.z, v3.w));
    float bv = fmaxf(fmaxf(m0, m1), fmaxf(m2, m3));

    const int lane = tid & 31, wid = tid >> 5;
#pragma unroll
    for (int o = 16; o; o >>= 1)
        bv = fmaxf(bv, __shfl_xor_sync(0xffffffffu, bv, o));

    __shared__ float s_w[8];
    __shared__ float s_m;
    if (lane == 0) s_w[wid] = bv;
    __syncthreads();
    if (tid < 8) {
        float x = s_w[tid];
#pragma unroll
        for (int o = 4; o; o >>= 1)
            x = fmaxf(x, __shfl_xor_sync(0xffu, x, o));
        if (tid == 0) s_m = x;
    }
    __syncthreads();

    const float m   = s_m;
    const float L2E = 1.4426950408889634f;
    const float mh  = m * L2E;

    float a0 = 0.f, a1 = 0.f, a2 = 0.f, a3 = 0.f;
    int   bi = 0x7fffffff;

#define ELEM(val, idx, acc)                                   \
    {                                                         \
        acc += exp2f(fmaf((val), L2E, -mh));                  \
        if ((val) == m) bi = min(bi, (idx));                  \
    }
    const int g0 = tid * 4, g1 = (tid + 256) * 4, g2 = (tid + 512) * 4, g3 = (tid + 768) * 4;
    ELEM(v0.x, g0 + 0, a0) ELEM(v0.y, g0 + 1, a1) ELEM(v0.z, g0 + 2, a2) ELEM(v0.w, g0 + 3, a3)
    ELEM(v1.x, g1 + 0, a0) ELEM(v1.y, g1 + 1, a1) ELEM(v1.z, g1 + 2, a2) ELEM(v1.w, g1 + 3, a3)
    ELEM(v2.x, g2 + 0, a0) ELEM(v2.y, g2 + 1, a1) ELEM(v2.z, g2 + 2, a2) ELEM(v2.w, g2 + 3, a3)
    ELEM(v3.x, g3 + 0, a0) ELEM(v3.y, g3 + 1, a1) ELEM(v3.z, g3 + 2, a2) ELEM(v3.w, g3 + 3, a3)
#undef ELEM

    float se = (a0 + a1) + (a2 + a3);
#pragma unroll
    for (int o = 16; o; o >>= 1) {
        se += __shfl_xor_sync(0xffffffffu, se, o);
        bi  = min(bi, __shfl_xor_sync(0xffffffffu, bi, o));
    }

    __shared__ float s_s[8];
    __shared__ int   s_i[8];
    if (lane == 0) { s_s[wid] = se; s_i[wid] = bi; }
    __syncthreads();
    if (tid < 8) {
        float S = s_s[tid];
        int   I = s_i[tid];
#pragma unroll
        for (int o = 4; o; o >>= 1) {
            S += __shfl_xor_sync(0xffu, S, o);
            I  = min(I, __shfl_xor_sync(0xffu, I, o));
        }
        if (tid == 0) {
            g_p[r]    = 1.0f / S;   // softmax prob at argmax == 1/sum(exp(x-max))
            g_pred[r] = I;
        }
    }
}

// ---------------------------------------------------------------------------
// Kernel 2: per batch row — segmentation with 512 threads (4 frames/thread):
// half the per-thread serial depth of the 256-thread version. Writes the
// DENSE metadata table (len=0 sentinel past the last segment).
// ---------------------------------------------------------------------------
__global__ __launch_bounds__(512) void seg_kernel(const int* __restrict__ lengths,
                                                  float* __restrict__ out_tail,
                                                  int write_tail)
{
    const int b   = blockIdx.x;
    const int tid = threadIdx.x;          // 0 .. 511
    const int L   = lengths[b];
    const int* pred = g_pred + b * T_;
    const float* pp = g_p    + b * T_;

    __shared__ int   sh_start[T_];
    __shared__ float sh_segp[T_];
    __shared__ int   sh_last[512];
    __shared__ int   wtot[16];

    // vectorized pred load: 4 ints per thread (one int4)
    const int4 pa = reinterpret_cast<const int4*>(pred)[tid];
    int pr[4] = {pa.x, pa.y, pa.z, pa.w};
    sh_last[tid] = pa.w;

    for (int i = tid; i < T_; i += 512) sh_segp[i] = 0.f;
    __syncthreads();

    const int t0 = tid * 4;
    int st[4], incl[4];
    int loc  = 0;
    int prev = (tid > 0) ? sh_last[tid - 1] : -1;
#pragma unroll
    for (int j = 0; j < 4; j++) {
        const int t = t0 + j;
        const int s = (t < L) && (t == 0 || pr[j] != prev);
        prev = pr[j];
        st[j] = s;
        loc  += s;
        incl[j] = loc;
    }

    // block-wide exclusive scan of per-thread start counts (16 warps)
    const int lane = tid & 31, wid = tid >> 5;
    int v = loc;
#pragma unroll
    for (int o = 1; o < 32; o <<= 1) {
        int n = __shfl_up_sync(0xffffffffu, v, o);
        if (lane >= o) v += n;
    }
    if (lane == 31) wtot[wid] = v;
    __syncthreads();
    if (tid < 16) {
        int w = wtot[tid];
#pragma unroll
        for (int o = 1; o < 16; o <<= 1) {
            int n = __shfl_up_sync(0xffffu, w, o);
            if (tid >= o) w += n;
        }
        wtot[tid] = w;  // inclusive warp totals
    }
    __syncthreads();
    const int total = wtot[15];
    const int excl  = (wid ? wtot[wid - 1] : 0) + (v - loc);

    // vectorized p load (one float4 per thread)
    const float4 f0 = reinterpret_cast<const float4*>(pp)[tid];
    const float pf[4] = {f0.x, f0.y, f0.z, f0.w};

    // per-frame segment id; record starts; accumulate seg_p
#pragma unroll
    for (int j = 0; j < 4; j++) {
        const int t = t0 + j;
        if (t < L) {
            const int sid = excl + incl[j] - 1;
            if (st[j]) sh_start[sid] = t;
            atomicAdd(&sh_segp[sid], pf[j]);
        }
    }
    __syncthreads();

    // dense metadata: valid segments get {start, len, inv}; rest get len=0
    for (int s = tid; s < T_; s += 512) {
        int4 mt;
        if (s < total) {
            const int start = sh_start[s];
            const int next  = (s + 1 < total) ? sh_start[s + 1] : L;
            mt = make_int4(start, next - start,
                           __float_as_int(1.0f / (sh_segp[s] + 1e-10f)), 0);
        } else {
            mt = make_int4(0, 0, 0, 0);
        }
        g_segmeta[b * T_ + s] = mt;
    }
    if (tid == 0) {
        g_newlen[b] = total;
        if (write_tail) out_tail[b] = (float)total;
    }
}

// ---------------------------------------------------------------------------
// Kernel 3: one WARP per output row (b, s); 8 rows per 256-thread block.
// Branch-free: len=0 rows fall through the loop and store zeros.
// Dependent chain: meta -> (p, hidden) -> store; p reads are L2-hot.
// ---------------------------------------------------------------------------
__global__ __launch_bounds__(256) void gather_kernel(const float* __restrict__ hidden,
                                                     float* __restrict__ out)
{
    const int warp = threadIdx.x >> 5;
    const int lane = threadIdx.x & 31;
    const int row  = blockIdx.x * 8 + warp;     // 0 .. B*T-1  (8 divides T)
    const int b    = row >> 11;                 // row / T_

    const int4  mt    = __ldg(&g_segmeta[row]);
    const int   start = mt.x;
    const int   len   = mt.y;
    const float inv   = __int_as_float(mt.z);

    const float4* hrow =
        reinterpret_cast<const float4*>(hidden) + ((size_t)(b * T_ + start)) * (D_ / 4);
    const float* pbase = g_p + b * T_ + start;

    float4 acc[4] = {make_float4(0.f, 0.f, 0.f, 0.f), make_float4(0.f, 0.f, 0.f, 0.f),
                     make_float4(0.f, 0.f, 0.f, 0.f), make_float4(0.f, 0.f, 0.f, 0.f)};
    for (int f = 0; f < len; ++f) {
        const float w = pbase[f] * inv;
#pragma unroll
        for (int k = 0; k < 4; k++) {
            const float4 h = __ldcs(&hrow[f * (D_ / 4) + lane + k * 32]);
            acc[k].x += w * h.x;
            acc[k].y += w * h.y;
            acc[k].z += w * h.z;
            acc[k].w += w * h.w;
        }
    }

    float4* orow = reinterpret_cast<float4*>(out) + (size_t)row * (D_ / 4);
#pragma unroll
    for (int k = 0; k < 4; k++) __stcs(&orow[lane + k * 32], acc[k]);
}

// ---------------------------------------------------------------------------
extern "C" void kernel_launch(void* const* d_in, const int* in_sizes, int n_in,
                              void* d_out, int out_size)
{
    const float* hidden  = (const float*)d_in[0];  // (B,T,D) f32
    const float* logits  = (const float*)d_in[1];  // (B,T,V) f32
    const int*   lengths = (const int*)d_in[2];    // (B,)   i32
    float* out = (float*)d_out;

    argmax_p_kernel<<<B_ * T_, 256>>>(logits);

    const int main_elems = B_ * T_ * D_;
    const int write_tail = (out_size >= main_elems + B_) ? 1 : 0;
    seg_kernel<<<B_, 512>>>(lengths, out + (size_t)main_elems, write_tail);

    gather_kernel<<<(B_ * T_) / 8, 256>>>(hidden, out);
}

// round 16
// speedup vs baseline: 1.0137x; 1.0031x over previous
#include <cuda_runtime.h>

#define B_ 16
#define T_ 2048
#define D_ 512
#define V_ 4096

// Scratch (static device globals — no allocation allowed in kernel_launch)
__device__ float g_p[B_ * T_];         // prob of argmax token per frame
__device__ int   g_pred[B_ * T_];      // argmax token per frame
__device__ int4  g_segmeta[B_ * T_];   // per (b,row): {start, len, bits(inv), 0}; len=0 => zero row
__device__ int   g_newlen[B_];         // per b: number of segments

// ---------------------------------------------------------------------------
// Kernel 1: per frame (B*T rows), argmax over V=4096 and p = 1/sum(exp(x-max))
// One block (256 thr) per row; max via FMNMX tree; index via exact equality.
// Measured at the sm_103a streaming ceiling (~6.55 TB/s, 82-83% DRAM).
// ---------------------------------------------------------------------------
__global__ __launch_bounds__(256) void argmax_p_kernel(const float* __restrict__ logits)
{
    const int r   = blockIdx.x;           // 0 .. B*T-1
    const int tid = threadIdx.x;
    const float4* row = reinterpret_cast<const float4*>(logits) + (size_t)r * (V_ / 4);

    // streaming loads (no reuse) — 4 LDG.128 in flight per thread
    const float4 v0 = __ldcs(&row[tid]);
    const float4 v1 = __ldcs(&row[tid + 256]);
    const float4 v2 = __ldcs(&row[tid + 512]);
    const float4 v3 = __ldcs(&row[tid + 768]);

    // thread-local max (pure FMNMX tree)
    const float m0 = fmaxf(fmaxf(v0.x, v0.y), fmaxf(v0.z, v0.w));
    const float m1 = fmaxf(fmaxf(v1.x, v1.y), fmaxf(v1.z, v1.w));
    const float m2 = fmaxf(fmaxf(v2.x, v2.y), fmaxf(v2.z, v2.w));
    const float m3 = fmaxf(fmaxf(v3.x, v3.y), fmaxf(v3.z, v3.w));
    float bv = fmaxf(fmaxf(m0, m1), fmaxf(m2, m3));

    const int lane = tid & 31, wid = tid >> 5;
#pragma unroll
    for (int o = 16; o; o >>= 1)
        bv = fmaxf(bv, __shfl_xor_sync(0xffffffffu, bv, o));

    __shared__ float s_w[8];
    __shared__ float s_m;
    if (lane == 0) s_w[wid] = bv;
    __syncthreads();
    if (tid < 8) {
        float x = s_w[tid];
#pragma unroll
        for (int o = 4; o; o >>= 1)
            x = fmaxf(x, __shfl_xor_sync(0xffu, x, o));
        if (tid == 0) s_m = x;
    }
    __syncthreads();

    const float m   = s_m;
    const float L2E = 1.4426950408889634f;
    const float mh  = m * L2E;

    float a0 = 0.f, a1 = 0.f, a2 = 0.f, a3 = 0.f;
    int   bi = 0x7fffffff;

#define ELEM(val, idx, acc)                                   \
    {                                                         \
        acc += exp2f(fmaf((val), L2E, -mh));                  \
        if ((val) == m) bi = min(bi, (idx));                  \
    }
    const int g0 = tid * 4, g1 = (tid + 256) * 4, g2 = (tid + 512) * 4, g3 = (tid + 768) * 4;
    ELEM(v0.x, g0 + 0, a0) ELEM(v0.y, g0 + 1, a1) ELEM(v0.z, g0 + 2, a2) ELEM(v0.w, g0 + 3, a3)
    ELEM(v1.x, g1 + 0, a0) ELEM(v1.y, g1 + 1, a1) ELEM(v1.z, g1 + 2, a2) ELEM(v1.w, g1 + 3, a3)
    ELEM(v2.x, g2 + 0, a0) ELEM(v2.y, g2 + 1, a1) ELEM(v2.z, g2 + 2, a2) ELEM(v2.w, g2 + 3, a3)
    ELEM(v3.x, g3 + 0, a0) ELEM(v3.y, g3 + 1, a1) ELEM(v3.z, g3 + 2, a2) ELEM(v3.w, g3 + 3, a3)
#undef ELEM

    float se = (a0 + a1) + (a2 + a3);
#pragma unroll
    for (int o = 16; o; o >>= 1) {
        se += __shfl_xor_sync(0xffffffffu, se, o);
        bi  = min(bi, __shfl_xor_sync(0xffffffffu, bi, o));
    }

    __shared__ float s_s[8];
    __shared__ int   s_i[8];
    if (lane == 0) { s_s[wid] = se; s_i[wid] = bi; }
    __syncthreads();
    if (tid < 8) {
        float S = s_s[tid];
        int   I = s_i[tid];
#pragma unroll
        for (int o = 4; o; o >>= 1) {
            S += __shfl_xor_sync(0xffu, S, o);
            I  = min(I, __shfl_xor_sync(0xffu, I, o));
        }
        if (tid == 0) {
            g_p[r]    = 1.0f / S;   // softmax prob at argmax == 1/sum(exp(x-max))
            g_pred[r] = I;
        }
    }
}

// ---------------------------------------------------------------------------
// Kernel 2: per batch row — segmentation with 512 threads (4 frames/thread):
// half the per-thread serial depth of the 256-thread version. Writes the
// DENSE metadata table (len=0 sentinel past the last segment).
// ---------------------------------------------------------------------------
__global__ __launch_bounds__(512) void seg_kernel(const int* __restrict__ lengths,
                                                  float* __restrict__ out_tail,
                                                  int write_tail)
{
    const int b   = blockIdx.x;
    const int tid = threadIdx.x;          // 0 .. 511
    const int L   = lengths[b];
    const int* pred = g_pred + b * T_;
    const float* pp = g_p    + b * T_;

    __shared__ int   sh_start[T_];
    __shared__ float sh_segp[T_];
    __shared__ int   sh_last[512];
    __shared__ int   wtot[16];

    // vectorized pred load: 4 ints per thread (one int4)
    const int4 pa = reinterpret_cast<const int4*>(pred)[tid];
    int pr[4] = {pa.x, pa.y, pa.z, pa.w};
    sh_last[tid] = pa.w;

    for (int i = tid; i < T_; i += 512) sh_segp[i] = 0.f;
    __syncthreads();

    const int t0 = tid * 4;
    int st[4], incl[4];
    int loc  = 0;
    int prev = (tid > 0) ? sh_last[tid - 1] : -1;
#pragma unroll
    for (int j = 0; j < 4; j++) {
        const int t = t0 + j;
        const int s = (t < L) && (t == 0 || pr[j] != prev);
        prev = pr[j];
        st[j] = s;
        loc  += s;
        incl[j] = loc;
    }

    // block-wide exclusive scan of per-thread start counts (16 warps)
    const int lane = tid & 31, wid = tid >> 5;
    int v = loc;
#pragma unroll
    for (int o = 1; o < 32; o <<= 1) {
        int n = __shfl_up_sync(0xffffffffu, v, o);
        if (lane >= o) v += n;
    }
    if (lane == 31) wtot[wid] = v;
    __syncthreads();
    if (tid < 16) {
        int w = wtot[tid];
#pragma unroll
        for (int o = 1; o < 16; o <<= 1) {
            int n = __shfl_up_sync(0xffffu, w, o);
            if (tid >= o) w += n;
        }
        wtot[tid] = w;  // inclusive warp totals
    }
    __syncthreads();
    const int total = wtot[15];
    const int excl  = (wid ? wtot[wid - 1] : 0) + (v - loc);

    // vectorized p load (one float4 per thread)
    const float4 f0 = reinterpret_cast<const float4*>(pp)[tid];
    const float pf[4] = {f0.x, f0.y, f0.z, f0.w};

    // per-frame segment id; record starts; accumulate seg_p
#pragma unroll
    for (int j = 0; j < 4; j++) {
        const int t = t0 + j;
        if (t < L) {
            const int sid = excl + incl[j] - 1;
            if (st[j]) sh_start[sid] = t;
            atomicAdd(&sh_segp[sid], pf[j]);
        }
    }
    __syncthreads();

    // dense metadata: valid segments get {start, len, inv}; rest get len=0
    for (int s = tid; s < T_; s += 512) {
        int4 mt;
        if (s < total) {
            const int start = sh_start[s];
            const int next  = (s + 1 < total) ? sh_start[s + 1] : L;
            mt = make_int4(start, next - start,
                           __float_as_int(1.0f / (sh_segp[s] + 1e-10f)), 0);
        } else {
            mt = make_int4(0, 0, 0, 0);
        }
        g_segmeta[b * T_ + s] = mt;
    }
    if (tid == 0) {
        g_newlen[b] = total;
        if (write_tail) out_tail[b] = (float)total;
    }
}

// ---------------------------------------------------------------------------
// Kernel 3: one WARP per output row (b, s); 8 rows per 256-thread block.
// Branch-free: len=0 rows fall through the loop and store zeros.
// Dependent chain: meta -> (p, hidden) -> store; p reads are L2-hot.
// ---------------------------------------------------------------------------
__global__ __launch_bounds__(256) void gather_kernel(const float* __restrict__ hidden,
                                                     float* __restrict__ out)
{
    const int warp = threadIdx.x >> 5;
    const int lane = threadIdx.x & 31;
    const int row  = blockIdx.x * 8 + warp;     // 0 .. B*T-1  (8 divides T)
    const int b    = row >> 11;                 // row / T_

    const int4  mt    = __ldg(&g_segmeta[row]);
    const int   start = mt.x;
    const int   len   = mt.y;
    const float inv   = __int_as_float(mt.z);

    const float4* hrow =
        reinterpret_cast<const float4*>(hidden) + ((size_t)(b * T_ + start)) * (D_ / 4);
    const float* pbase = g_p + b * T_ + start;

    float4 acc[4] = {make_float4(0.f, 0.f, 0.f, 0.f), make_float4(0.f, 0.f, 0.f, 0.f),
                     make_float4(0.f, 0.f, 0.f, 0.f), make_float4(0.f, 0.f, 0.f, 0.f)};
    for (int f = 0; f < len; ++f) {
        const float w = pbase[f] * inv;
#pragma unroll
        for (int k = 0; k < 4; k++) {
            const float4 h = __ldcs(&hrow[f * (D_ / 4) + lane + k * 32]);
            acc[k].x += w * h.x;
            acc[k].y += w * h.y;
            acc[k].z += w * h.z;
            acc[k].w += w * h.w;
        }
    }

    float4* orow = reinterpret_cast<float4*>(out) + (size_t)row * (D_ / 4);
#pragma unroll
    for (int k = 0; k < 4; k++) __stcs(&orow[lane + k * 32], acc[k]);
}

// ---------------------------------------------------------------------------
extern "C" void kernel_launch(void* const* d_in, const int* in_sizes, int n_in,
                              void* d_out, int out_size)
{
    const float* hidden  = (const float*)d_in[0];  // (B,T,D) f32
    const float* logits  = (const float*)d_in[1];  // (B,T,V) f32
    const int*   lengths = (const int*)d_in[2];    // (B,)   i32
    float* out = (float*)d_out;

    argmax_p_kernel<<<B_ * T_, 256>>>(logits);

    const int main_elems = B_ * T_ * D_;
    const int write_tail = (out_size >= main_elems + B_) ? 1 : 0;
    seg_kernel<<<B_, 512>>>(lengths, out + (size_t)main_elems, write_tail);

    gather_kernel<<<(B_ * T_) / 8, 256>>>(hidden, out);
}